// round 1
// baseline (speedup 1.0000x reference)
#include <cuda_runtime.h>

#define SDIM 512
#define BDIM 8
#define KMAX 16
#define EMPTY_DIST 362.1f

// Device-global scratch (no allocations allowed)
__device__ float g_pty[BDIM][KMAX];
__device__ float g_ptx[BDIM][KMAX];
__device__ int   g_cnt[BDIM];
__device__ float g_sum[BDIM];          // per-image sum(pred * _distance_unnorm)
__device__ unsigned int g_maxb[BDIM];  // per-image max(_distance) as uint bits (nonneg)
__device__ float g_grad;               // global gradient sum

__global__ void init_kernel() {
    int i = threadIdx.x;
    if (i < BDIM) { g_cnt[i] = 0; g_sum[i] = 0.0f; g_maxb[i] = 0u; }
    if (i == 0) g_grad = 0.0f;
}

// Collect coordinates of all nonzero pt_label pixels (<=16 per image).
__global__ void find_points(const float* __restrict__ pt) {
    int b = blockIdx.y;
    const float* p = pt + (size_t)b * SDIM * SDIM;
    int stride = blockDim.x * gridDim.x;
    for (int i = blockIdx.x * blockDim.x + threadIdx.x; i < SDIM * SDIM; i += stride) {
        if (fabsf(p[i]) > 0.0f) {
            int slot = atomicAdd(&g_cnt[b], 1);
            if (slot < KMAX) {
                g_pty[b][slot] = (float)(i / SDIM);
                g_ptx[b][slot] = (float)(i % SDIM);
            }
        }
    }
}

__device__ __forceinline__ float warp_sum(float v) {
    #pragma unroll
    for (int o = 16; o > 0; o >>= 1) v += __shfl_xor_sync(0xffffffffu, v, o);
    return v;
}
__device__ __forceinline__ float warp_max(float v) {
    #pragma unroll
    for (int o = 16; o > 0; o >>= 1) v = fmaxf(v, __shfl_xor_sync(0xffffffffu, v, o));
    return v;
}

// Fused kernel: block = (32,8) threads, covers a 32x32 tile of one image.
// Each thread handles 4 rows (ty, ty+8, ty+16, ty+24).
__global__ __launch_bounds__(256) void fused_kernel(
    const float* __restrict__ pred,
    const float* __restrict__ ori)
{
    __shared__ float img[34][35];      // (ori*pred) tile with 1-halo, padded row
    __shared__ float spy[KMAX], spx[KMAX];
    __shared__ int   scnt;
    __shared__ float red_s[8], red_m[8], red_g[8];

    int b   = blockIdx.z;
    int tx0 = blockIdx.x * 32;
    int ty0 = blockIdx.y * 32;
    int tid = threadIdx.y * 32 + threadIdx.x;

    const float* pb = pred + (size_t)b * SDIM * SDIM;
    const float* ob = ori  + (size_t)b * SDIM * SDIM;

    if (tid == 0) scnt = min(g_cnt[b], KMAX);
    if (tid < KMAX) { spy[tid] = g_pty[b][tid]; spx[tid] = g_ptx[b][tid]; }

    // Load 34x34 tile of ori*pred (zeros outside image; those values are only
    // consumed by border pixels whose gradient is skipped anyway).
    for (int i = tid; i < 34 * 34; i += 256) {
        int ly = i / 34, lx = i % 34;
        int gy = ty0 - 1 + ly, gx = tx0 - 1 + lx;
        float v = 0.0f;
        if (gy >= 0 && gy < SDIM && gx >= 0 && gx < SDIM) {
            int idx = gy * SDIM + gx;
            v = pb[idx] * ob[idx];
        }
        img[ly][lx] = v;
    }
    __syncthreads();

    int   cnt = scnt;
    int   x   = tx0 + threadIdx.x;
    float fx  = (float)x;
    float lsum = 0.0f, lmax = 0.0f, lgrad = 0.0f;

    #pragma unroll
    for (int r = 0; r < 4; r++) {
        int lyy = threadIdx.y + r * 8;
        int y   = ty0 + lyy;
        float fy = (float)y;

        // --- distance term ---
        float dd;
        if (cnt > 0) {
            float dmin2 = 3.4e38f;
            #pragma unroll 4
            for (int k = 0; k < cnt; k++) {
                float dy = fy - spy[k];
                float dx = fx - spx[k];
                float d2 = fmaf(dy, dy, dx * dx);
                dmin2 = fminf(dmin2, d2);
            }
            float dist = sqrtf(dmin2);
            dd = (dist > 1.0f) ? (dist - 1.0f) : 0.0f;   // distance_thre = 1
        } else {
            dd = EMPTY_DIST - 1.0f;
        }
        lmax = fmaxf(lmax, dd);
        lsum += pb[y * SDIM + x] * dd;

        // --- gradient term (interior pixels only; border rows/cols zeroed) ---
        if (y > 0 && y < SDIM - 1 && x > 0 && x < SDIM - 1) {
            int ly = lyy + 1, lx = threadIdx.x + 1;
            float a  = img[ly - 1][lx - 1];
            float bb = img[ly - 1][lx    ];
            float c  = img[ly - 1][lx + 1];
            float d  = img[ly    ][lx - 1];
            float f  = img[ly    ][lx + 1];
            float gg = img[ly + 1][lx - 1];
            float h  = img[ly + 1][lx    ];
            float ii = img[ly + 1][lx + 1];
            float f0 = (c - a) + 2.0f * (f - d) + (ii - gg);
            float f1 = (a - gg) + 2.0f * (bb - h) + (c - ii);
            float f2 = 2.0f * (a - ii) + (bb - h) + (d - f);
            float f3 = (bb - h) + 2.0f * (c - gg) + (f - d);
            lgrad += fmaxf(fmaxf(fabsf(f0), fabsf(f1)),
                           fmaxf(fabsf(f2), fabsf(f3)));
        }
    }

    // Block reduction: warp shuffle -> shared -> one atomic per block
    float ws = warp_sum(lsum);
    float wm = warp_max(lmax);
    float wg = warp_sum(lgrad);
    int warp = tid >> 5, lane = tid & 31;
    if (lane == 0) { red_s[warp] = ws; red_m[warp] = wm; red_g[warp] = wg; }
    __syncthreads();
    if (tid == 0) {
        float bs = 0.0f, bm = 0.0f, bg = 0.0f;
        #pragma unroll
        for (int w = 0; w < 8; w++) {
            bs += red_s[w];
            bm = fmaxf(bm, red_m[w]);
            bg += red_g[w];
        }
        atomicAdd(&g_sum[b], bs);
        atomicMax(&g_maxb[b], __float_as_uint(bm));
        atomicAdd(&g_grad, bg);
    }
}

__global__ void finalize_kernel(float* __restrict__ out) {
    if (threadIdx.x == 0) {
        float dl = 0.0f;
        #pragma unroll
        for (int b = 0; b < BDIM; b++) {
            float m = __uint_as_float(g_maxb[b]);
            dl += g_sum[b] / m;
        }
        float denom = (float)SDIM * (float)SDIM * (float)BDIM;
        out[0] = dl / denom;
        out[1] = g_grad / denom;
    }
}

extern "C" void kernel_launch(void* const* d_in, const int* in_sizes, int n_in,
                              void* d_out, int out_size) {
    const float* pred = (const float*)d_in[0];
    const float* ptl  = (const float*)d_in[1];
    const float* ori  = (const float*)d_in[2];
    float* out = (float*)d_out;

    init_kernel<<<1, 32>>>();
    find_points<<<dim3(64, BDIM), 256>>>(ptl);
    fused_kernel<<<dim3(SDIM / 32, SDIM / 32, BDIM), dim3(32, 8)>>>(pred, ori);
    finalize_kernel<<<1, 32>>>(out);
}

// round 2
// speedup vs baseline: 1.2341x; 1.2341x over previous
#include <cuda_runtime.h>
#include <float.h>

#define SDIM 512
#define BDIM 8
#define KMAX 16
#define EMPTY_DIST 362.1f
#define NFUSED (16 * 16 * BDIM)   // 2048 fused blocks

// Device-global scratch (zero at module load; self-reset by last fused block
// each call, so every graph replay starts from the identical zero state).
__device__ float4   g_pts[BDIM][KMAX];   // (-2y, -2x, y*y+x*x, 0) per point
__device__ int      g_cnt[BDIM];
__device__ float    g_sum[BDIM];         // per-image sum(pred * dd)
__device__ unsigned g_maxb[BDIM];        // per-image max(dd) as uint bits
__device__ float    g_grad;              // global gradient sum
__device__ unsigned g_done;              // completion ticket

// ---------------------------------------------------------------------------
// Kernel 1: scan pt_label, record up to 16 highlight points per image with
// precomputed distance-expansion coefficients.
__global__ void find_points(const float* __restrict__ pt) {
    int b = blockIdx.y;
    const float4* p4 = (const float4*)(pt + (size_t)b * SDIM * SDIM);
    const int n4 = SDIM * SDIM / 4;
    int stride = blockDim.x * gridDim.x;
    for (int c = blockIdx.x * blockDim.x + threadIdx.x; c < n4; c += stride) {
        float4 v = p4[c];
        float vv[4] = {v.x, v.y, v.z, v.w};
        #pragma unroll
        for (int j = 0; j < 4; j++) {
            if (vv[j] != 0.0f) {
                int slot = atomicAdd(&g_cnt[b], 1);
                if (slot < KMAX) {
                    int pix = c * 4 + j;
                    float y = (float)(pix >> 9);
                    float x = (float)(pix & 511);
                    g_pts[b][slot] = make_float4(-2.0f * y, -2.0f * x,
                                                 fmaf(y, y, x * x), 0.0f);
                }
            }
        }
    }
}

// ---------------------------------------------------------------------------
__device__ __forceinline__ float warp_sum(float v) {
    #pragma unroll
    for (int o = 16; o > 0; o >>= 1) v += __shfl_xor_sync(0xffffffffu, v, o);
    return v;
}
__device__ __forceinline__ float warp_max(float v) {
    #pragma unroll
    for (int o = 16; o > 0; o >>= 1) v = fmaxf(v, __shfl_xor_sync(0xffffffffu, v, o));
    return v;
}

// Kernel 2: fused distance + gradient + reductions + (last block) finalize.
// Block = (32,8), one 32x32 tile per block, each thread owns 4 rows.
__global__ __launch_bounds__(256) void fused_kernel(
    const float* __restrict__ pred,
    const float* __restrict__ ori,
    float* __restrict__ out)
{
    __shared__ float  img[34][35];       // (ori*pred) tile with 1-halo
    __shared__ float4 spts[KMAX];
    __shared__ float  red_s[8], red_m[8], red_g[8];

    int b   = blockIdx.z;
    int tx0 = blockIdx.x * 32;
    int ty0 = blockIdx.y * 32;
    int tid = threadIdx.y * 32 + threadIdx.x;

    const float* pb = pred + (size_t)b * SDIM * SDIM;
    const float* ob = ori  + (size_t)b * SDIM * SDIM;

    if (tid < KMAX) spts[tid] = g_pts[b][tid];
    int cnt = min(g_cnt[b], KMAX);

    // Load 34x34 halo tile of ori*pred (zeros outside; those feed only
    // border pixels whose gradient is zeroed anyway).
    for (int i = tid; i < 34 * 34; i += 256) {
        int ly = i / 34, lx = i % 34;
        int gy = ty0 - 1 + ly, gx = tx0 - 1 + lx;
        float v = 0.0f;
        if (gy >= 0 && gy < SDIM && gx >= 0 && gx < SDIM) {
            int idx = gy * SDIM + gx;
            v = pb[idx] * ob[idx];
        }
        img[ly][lx] = v;
    }
    __syncthreads();

    int   x   = tx0 + threadIdx.x;
    float fx  = (float)x;
    float fx2 = fx * fx;

    float fyr[4], r2[4], tmin[4];
    #pragma unroll
    for (int r = 0; r < 4; r++) {
        fyr[r]  = (float)(ty0 + threadIdx.y + r * 8);
        r2[r]   = fmaf(fyr[r], fyr[r], fx2);
        tmin[r] = FLT_MAX;
    }

    // min_k d^2 = r2 + min_k [ (-2sy)*fy + (-2sx)*fx + (sy^2+sx^2) ]
    #pragma unroll 4
    for (int k = 0; k < cnt; k++) {
        float4 p = spts[k];
        float pk = fmaf(p.y, fx, p.z);
        #pragma unroll
        for (int r = 0; r < 4; r++)
            tmin[r] = fminf(tmin[r], fmaf(p.x, fyr[r], pk));
    }

    float lsum = 0.0f, lmax = 0.0f, lgrad = 0.0f;

    #pragma unroll
    for (int r = 0; r < 4; r++) {
        int lyy = threadIdx.y + r * 8;
        int y   = ty0 + lyy;

        float dd;
        if (cnt > 0) {
            float d2 = fmaxf(r2[r] + tmin[r], 0.0f);
            dd = fmaxf(sqrtf(d2) - 1.0f, 0.0f);   // distance_thre = 1
        } else {
            dd = EMPTY_DIST - 1.0f;
        }
        lmax = fmaxf(lmax, dd);
        lsum += pb[y * SDIM + x] * dd;

        if (y > 0 && y < SDIM - 1 && x > 0 && x < SDIM - 1) {
            int ly = lyy + 1, lx = threadIdx.x + 1;
            float a  = img[ly - 1][lx - 1];
            float bb = img[ly - 1][lx    ];
            float c  = img[ly - 1][lx + 1];
            float d  = img[ly    ][lx - 1];
            float f  = img[ly    ][lx + 1];
            float gg = img[ly + 1][lx - 1];
            float h  = img[ly + 1][lx    ];
            float ii = img[ly + 1][lx + 1];
            float f0 = (c - a) + 2.0f * (f - d) + (ii - gg);
            float f1 = (a - gg) + 2.0f * (bb - h) + (c - ii);
            float f2 = 2.0f * (a - ii) + (bb - h) + (d - f);
            float f3 = (bb - h) + 2.0f * (c - gg) + (f - d);
            lgrad += fmaxf(fmaxf(fabsf(f0), fabsf(f1)),
                           fmaxf(fabsf(f2), fabsf(f3)));
        }
    }

    // Block reduction -> one atomic set per block
    float ws = warp_sum(lsum);
    float wm = warp_max(lmax);
    float wg = warp_sum(lgrad);
    int warp = tid >> 5, lane = tid & 31;
    if (lane == 0) { red_s[warp] = ws; red_m[warp] = wm; red_g[warp] = wg; }
    __syncthreads();

    if (tid == 0) {
        float bs = 0.0f, bm = 0.0f, bg = 0.0f;
        #pragma unroll
        for (int w = 0; w < 8; w++) {
            bs += red_s[w];
            bm = fmaxf(bm, red_m[w]);
            bg += red_g[w];
        }
        atomicAdd(&g_sum[b], bs);
        atomicMax(&g_maxb[b], __float_as_uint(bm));
        atomicAdd(&g_grad, bg);

        // Completion ticket: last block finalizes and resets all state.
        __threadfence();
        unsigned ticket = atomicAdd(&g_done, 1u);
        if (ticket == NFUSED - 1) {
            float dl = 0.0f;
            #pragma unroll
            for (int i = 0; i < BDIM; i++) {
                float s = atomicAdd(&g_sum[i], 0.0f);       // coherent read
                float m = __uint_as_float(atomicMax(&g_maxb[i], 0u));
                dl += s / m;
            }
            float gr = atomicAdd(&g_grad, 0.0f);
            float denom = (float)SDIM * (float)SDIM * (float)BDIM;
            out[0] = dl / denom;
            out[1] = gr / denom;

            // Reset for next graph replay (back to module-load zero state).
            #pragma unroll
            for (int i = 0; i < BDIM; i++) {
                g_cnt[i]  = 0;
                g_sum[i]  = 0.0f;
                g_maxb[i] = 0u;
            }
            g_grad = 0.0f;
            __threadfence();
            g_done = 0u;
        }
    }
}

extern "C" void kernel_launch(void* const* d_in, const int* in_sizes, int n_in,
                              void* d_out, int out_size) {
    const float* pred = (const float*)d_in[0];
    const float* ptl  = (const float*)d_in[1];
    const float* ori  = (const float*)d_in[2];
    float* out = (float*)d_out;

    find_points<<<dim3(64, BDIM), 256>>>(ptl);
    fused_kernel<<<dim3(SDIM / 32, SDIM / 32, BDIM), dim3(32, 8)>>>(pred, ori, out);
}

// round 4
// speedup vs baseline: 1.3902x; 1.1265x over previous
#include <cuda_runtime.h>
#include <float.h>

#define SDIM 512
#define BDIM 8
#define KMAX 16
#define EMPTY_DIST 362.1f
#define NFUSED (16 * 16 * BDIM)   // 2048 fused blocks

// Device-global scratch (zero at module load; self-reset by last fused block
// each call so every graph replay starts from identical zero state).
__device__ float4   g_pts[BDIM][KMAX];   // (-2y, -2x, y*y+x*x, 0) per point
__device__ int      g_cnt[BDIM];
__device__ float    g_sum[BDIM];
__device__ unsigned g_maxb[BDIM];
__device__ float    g_grad;
__device__ unsigned g_done;

// ---------------------------------------------------------------------------
__global__ void find_points(const float* __restrict__ pt) {
    int b = blockIdx.y;
    const float4* p4 = (const float4*)(pt + (size_t)b * SDIM * SDIM);
    const int n4 = SDIM * SDIM / 4;
    int stride = blockDim.x * gridDim.x;
    for (int c = blockIdx.x * blockDim.x + threadIdx.x; c < n4; c += stride) {
        float4 v = p4[c];
        float vv[4] = {v.x, v.y, v.z, v.w};
        #pragma unroll
        for (int j = 0; j < 4; j++) {
            if (vv[j] != 0.0f) {
                int slot = atomicAdd(&g_cnt[b], 1);
                if (slot < KMAX) {
                    int pix = c * 4 + j;
                    float y = (float)(pix >> 9);
                    float x = (float)(pix & 511);
                    g_pts[b][slot] = make_float4(-2.0f * y, -2.0f * x,
                                                 fmaf(y, y, x * x), 0.0f);
                }
            }
        }
    }
}

// ---------------------------------------------------------------------------
__device__ __forceinline__ float warp_sum(float v) {
    #pragma unroll
    for (int o = 16; o > 0; o >>= 1) v += __shfl_xor_sync(0xffffffffu, v, o);
    return v;
}
__device__ __forceinline__ float warp_max(float v) {
    #pragma unroll
    for (int o = 16; o > 0; o >>= 1) v = fmaxf(v, __shfl_xor_sync(0xffffffffu, v, o));
    return v;
}

// Distance accumulation body (shared by unrolled / dynamic paths)
#define DIST_BODY(k)                                              \
    {                                                             \
        float4 p = spts[k];                                       \
        float pk = fmaf(p.y, fx, p.z);                            \
        _Pragma("unroll")                                         \
        for (int r = 0; r < 4; r++)                               \
            tmin[r] = fminf(tmin[r], fmaf(p.x, fyr[r], pk));      \
    }

// Fused kernel. Block=(32,8); tile 32x32; thread (tx,ty) owns 4 CONSECUTIVE
// rows 4*ty..4*ty+3 of column tx. Interior smem stores come from the owning
// thread (coalesced, pred kept in regs); only the 132 perimeter halo elements
// take the slow path.
__global__ __launch_bounds__(256) void fused_kernel(
    const float* __restrict__ pred,
    const float* __restrict__ ori,
    float* __restrict__ out)
{
    __shared__ float  img[34][35];
    __shared__ float4 spts[KMAX];
    __shared__ float  red_s[8], red_m[8], red_g[8];

    int tx  = threadIdx.x, ty = threadIdx.y;
    int b   = blockIdx.z;
    int tx0 = blockIdx.x * 32;
    int ty0 = blockIdx.y * 32;
    int tid = ty * 32 + tx;

    const float* pb = pred + (size_t)b * SDIM * SDIM;
    const float* ob = ori  + (size_t)b * SDIM * SDIM;

    if (tid < KMAX) spts[tid] = g_pts[b][tid];
    int cnt = min(g_cnt[b], KMAX);

    int x  = tx0 + tx;
    int y0 = ty0 + 4 * ty;

    // Interior: each thread loads its own 4 pixels of pred & ori, stores the
    // product, keeps pred in registers.
    float predv[4];
    #pragma unroll
    for (int r = 0; r < 4; r++) {
        int idx = (y0 + r) * SDIM + x;
        float p = pb[idx];
        predv[r] = p;
        img[4 * ty + 1 + r][tx + 1] = p * ob[idx];
    }

    // Perimeter halo: 132 elements, threads 0..131, no divisions.
    if (tid < 132) {
        int ly, lx;
        if      (tid < 34)  { ly = 0;             lx = tid;       }
        else if (tid < 68)  { ly = 33;            lx = tid - 34;  }
        else if (tid < 100) { ly = tid - 68 + 1;  lx = 0;         }
        else                { ly = tid - 100 + 1; lx = 33;        }
        int gy = ty0 - 1 + ly, gx = tx0 - 1 + lx;
        float v = 0.0f;
        if (gy >= 0 && gy < SDIM && gx >= 0 && gx < SDIM) {
            int idx = gy * SDIM + gx;
            v = pb[idx] * ob[idx];
        }
        img[ly][lx] = v;
    }

    // ---- distance: min_k d^2 = (fy^2+fx^2) + min_k[(-2sy)fy + (-2sx)fx + c]
    float fx  = (float)x;
    float fx2 = fx * fx;
    float fyr[4], tmin[4];
    #pragma unroll
    for (int r = 0; r < 4; r++) {
        fyr[r]  = (float)(y0 + r);
        tmin[r] = FLT_MAX;
    }

    __syncthreads();

    if (cnt == KMAX) {
        #pragma unroll
        for (int k = 0; k < KMAX; k++) DIST_BODY(k)
    } else {
        for (int k = 0; k < cnt; k++) DIST_BODY(k)
    }

    float lsum = 0.0f, lmax = 0.0f, lgrad = 0.0f;

    // Rolling 3x3 window over 4 consecutive rows: 3 new LDS per row.
    int lx = tx + 1;
    float t0 = img[4 * ty + 0][lx - 1], t1 = img[4 * ty + 0][lx], t2 = img[4 * ty + 0][lx + 1];
    float m0 = img[4 * ty + 1][lx - 1], m1 = img[4 * ty + 1][lx], m2 = img[4 * ty + 1][lx + 1];

    bool x_in = (x >= 1) && (x <= SDIM - 2);

    #pragma unroll
    for (int r = 0; r < 4; r++) {
        int y  = y0 + r;
        int ly = 4 * ty + 2 + r;
        float b0 = img[ly][lx - 1], b1 = img[ly][lx], b2 = img[ly][lx + 1];

        // distance term
        float dd;
        if (cnt > 0) {
            float d2 = fmaxf(fmaf(fyr[r], fyr[r], fx2) + tmin[r], 0.0f);
            dd = fmaxf(sqrtf(d2) - 1.0f, 0.0f);   // distance_thre = 1
        } else {
            dd = EMPTY_DIST - 1.0f;
        }
        lmax = fmaxf(lmax, dd);
        lsum = fmaf(predv[r], dd, lsum);

        // gradient term: u=b-h, v=f-d, w=a-i, z=c-g
        float u = t1 - b1;
        float v = m2 - m0;
        float w = t0 - b2;
        float z = t2 - b0;
        float f0 = fmaf(2.0f, v, z - w);
        float f1 = fmaf(2.0f, u, z + w);
        float f2 = fmaf(2.0f, w, u - v);
        float f3 = fmaf(2.0f, z, u + v);
        float m4 = fmaxf(fmaxf(fabsf(f0), fabsf(f1)),
                         fmaxf(fabsf(f2), fabsf(f3)));
        bool in = x_in && (y >= 1) && (y <= SDIM - 2);
        lgrad += in ? m4 : 0.0f;

        // roll window
        t0 = m0; t1 = m1; t2 = m2;
        m0 = b0; m1 = b1; m2 = b2;
    }

    // Block reduction -> one atomic set per block
    float ws = warp_sum(lsum);
    float wm = warp_max(lmax);
    float wg = warp_sum(lgrad);
    int warp = tid >> 5, lane = tid & 31;
    if (lane == 0) { red_s[warp] = ws; red_m[warp] = wm; red_g[warp] = wg; }
    __syncthreads();

    if (tid == 0) {
        float bs = 0.0f, bm = 0.0f, bg = 0.0f;
        #pragma unroll
        for (int w2 = 0; w2 < 8; w2++) {
            bs += red_s[w2];
            bm = fmaxf(bm, red_m[w2]);
            bg += red_g[w2];
        }
        atomicAdd(&g_sum[b], bs);
        atomicMax(&g_maxb[b], __float_as_uint(bm));
        atomicAdd(&g_grad, bg);

        __threadfence();
        unsigned ticket = atomicAdd(&g_done, 1u);
        if (ticket == NFUSED - 1) {
            float dl = 0.0f;
            #pragma unroll
            for (int i = 0; i < BDIM; i++) {
                float s = atomicAdd(&g_sum[i], 0.0f);
                float m = __uint_as_float(atomicMax(&g_maxb[i], 0u));
                dl += s / m;
            }
            float gr = atomicAdd(&g_grad, 0.0f);
            float denom = (float)SDIM * (float)SDIM * (float)BDIM;
            out[0] = dl / denom;
            out[1] = gr / denom;

            #pragma unroll
            for (int i = 0; i < BDIM; i++) {
                g_cnt[i]  = 0;
                g_sum[i]  = 0.0f;
                g_maxb[i] = 0u;
            }
            g_grad = 0.0f;
            __threadfence();
            g_done = 0u;
        }
    }
}

extern "C" void kernel_launch(void* const* d_in, const int* in_sizes, int n_in,
                              void* d_out, int out_size) {
    const float* pred = (const float*)d_in[0];
    const float* ptl  = (const float*)d_in[1];
    const float* ori  = (const float*)d_in[2];
    float* out = (float*)d_out;

    find_points<<<dim3(64, BDIM), 256>>>(ptl);
    fused_kernel<<<dim3(SDIM / 32, SDIM / 32, BDIM), dim3(32, 8)>>>(pred, ori, out);
}